// round 14
// baseline (speedup 1.0000x reference)
#include <cuda_runtime.h>
#include <math.h>

#define N3INV (1.0f/262144.0f)
typedef unsigned long long u64;

// ---------------- scratch (static device memory; no allocations) ----------------
__device__ float2 g_Bm[8*24*12*1024];    // 19 MB: fwd Y out, mode-major [((b*24+ky)*12+kz)*1024 + c*64+x]
__device__ float2 g_Bf[8*16*64*24*12];   // 19 MB: inv-X out [(bo*24+ky)*64+x][kz]
__device__ float2 g_W [24*24*12*16*16];  // 14 MB: repacked weights, mode-major
__device__ u64    g_twTpkT[32*12];       // fwd T: (c, -s) packed, TRANSPOSED [t1*12+k] (broadcast use)
__device__ u64    g_twTi2 [12*32];       // inv T: (A, B) packed, [k*32+t]  (per-lane stride-1 use)
__device__ float2 g_twXY [24*33];        // X/Y: (c, s)  [padded stride 33] (fwd + inv shared)

// ---------------- f32x2 packed helpers ----------------
__device__ __forceinline__ u64 pk2(float lo, float hi){
    u64 r; asm("mov.b64 %0, {%1,%2};" : "=l"(r) : "f"(lo), "f"(hi)); return r;
}
__device__ __forceinline__ void fma2(u64& d, u64 a, u64 b){
    asm("fma.rn.f32x2 %0, %1, %2, %0;" : "+l"(d) : "l"(a), "l"(b));
}
__device__ __forceinline__ u64 add2(u64 a, u64 b){
    u64 d; asm("add.rn.f32x2 %0, %1, %2;" : "=l"(d) : "l"(a), "l"(b)); return d;
}
__device__ __forceinline__ float2 unpk2(u64 v){
    float2 f; asm("mov.b64 {%0,%1}, %2;" : "=f"(f.x), "=f"(f.y) : "l"(v)); return f;
}

// ---------------- init + repack: blocks 0-575 repack (one quadrant each), block 576 twiddles ----------------
__global__ void __launch_bounds__(256) k_initrepack(const float* __restrict__ w1, const float* __restrict__ w2,
                                                    const float* __restrict__ w3, const float* __restrict__ w4) {
    int tid = threadIdx.x;
    if (blockIdx.x == 576) {
        for (int idx = tid; idx < 384 + 792; idx += 256) {
            if (idx < 384) {
                int k = idx >> 5, t = idx & 31;
                float s, c;
                sincospif((float)((k * t) & 63) / 32.0f, &s, &c);
                g_twTpkT[t*12 + k] = pk2(c, -s);
                g_twTi2[idx] = (k == 0) ? pk2(N3INV, 0.0f)
                                        : pk2(2.0f*c*N3INV, -2.0f*s*N3INV);
            } else {
                int r = idx - 384;
                int j = r / 33, u = r % 33;
                int uu = (u < 32) ? u : 0;
                int f = (j < 12) ? j : j + 40;   // freqs 0..11, 52..63
                float s, c;
                sincospif((float)((f * uu) & 63) / 32.0f, &s, &c);
                g_twXY[r] = make_float2(c, s);
            }
        }
        return;
    }
    int q  = blockIdx.x / 144;
    int rm = blockIdx.x % 144;
    int jx = rm / 12, jy = rm % 12;
    const float* w = (q == 0) ? w1 : (q == 1) ? w2 : (q == 2) ? w3 : w4;
    const float4* src = (const float4*)(w + ((size_t)tid*1728 + (jx*12 + jy)*12)*2);
    float2 r[12];
#pragma unroll
    for (int j = 0; j < 6; j++) {
        float4 v = src[j];
        r[2*j]   = make_float2(v.x, v.y);
        r[2*j+1] = make_float2(v.z, v.w);
    }
    int kxi = jx + ((q & 1) ? 12 : 0);
    int kyi = jy + ((q & 2) ? 12 : 0);
    float2* dst = g_W + ((size_t)(kxi*24 + kyi)*12)*256 + tid;
#pragma unroll
    for (int j = 0; j < 12; j++) dst[j*256] = r[j];
}

// ---------------- kA2: fused T-DFT (radix-2) + Y-DFT (radix-2)  [R12 verbatim] ----------------
#define KA2_SMEM (2*4160*4 + 2*792*8 + 384*8 + 792*8)
__global__ void __launch_bounds__(288, 4) kA2(const float* __restrict__ x) {
    extern __shared__ char smraw[];
    float*  sx  = (float*)smraw;
    float2* sA  = (float2*)(smraw + 2*4160*4);
    u64*    stT = (u64*)(smraw + 2*4160*4 + 2*792*8);          // transposed [t1*12+k]
    float2* stY = (float2*)(smraw + 2*4160*4 + 2*792*8 + 384*8);
    float2* sEO = (float2*)sx;           // reused after T-phase: [sl*804 + p*396 + k*33 + y1]

    int slab0 = blockIdx.x * 2;
    int tid = threadIdx.x;

    const float4* xs = (const float4*)(x + (size_t)slab0 * 4096);
    for (int i = tid; i < 2048; i += 288) {
        float4 v = xs[i];
        int sl = i >> 10, r = i & 1023;
        int yy = r >> 4, t4 = (r & 15) * 4;
        float* row = &sx[sl*4160 + yy*65 + t4];
        row[0] = v.x; row[1] = v.y; row[2] = v.z; row[3] = v.w;
    }
    for (int i = tid; i < 384; i += 288) stT[i] = g_twTpkT[i];
    for (int i = tid; i < 792; i += 288) stY[i] = g_twXY[i];
    __syncthreads();

    if (tid < 256) {
        int sl = tid >> 7, g = (tid >> 6) & 1, yy = tid & 63;
        int kb = g * 6;
        const float* row = &sx[sl*4160 + yy*65];
        u64 acc[6];
#pragma unroll
        for (int j = 0; j < 6; j++) acc[j] = 0ull;
#pragma unroll 4
        for (int t1 = 0; t1 < 32; t1++) {
            float a = row[t1], b = row[t1 + 32];
            float E = a + b, O = a - b;
            u64 pE = pk2(E, E), pO = pk2(O, O);
            const u64* tw = stT + t1*12 + kb;
#pragma unroll
            for (int j2 = 0; j2 < 3; j2++) {
                ulonglong2 tv = *(const ulonglong2*)(tw + 2*j2);
                fma2(acc[2*j2],     tv.x, pE);
                fma2(acc[2*j2 + 1], tv.y, pO);
            }
        }
        float2* dst = sA + sl*792 + yy;
#pragma unroll
        for (int j = 0; j < 6; j++) dst[(kb + j)*66] = unpk2(acc[j]);
    }
    __syncthreads();

    for (int i = tid; i < 768; i += 288) {
        int sl = (i >= 384);
        int r  = i - sl*384;                      // r = k*32 + y1
        int k = r >> 5, y1 = r & 31;
        float2 a = sA[sl*792 + k*66 + y1];
        float2 b = sA[sl*792 + k*66 + 32 + y1];
        sEO[sl*804 + k*33 + y1]       = make_float2(a.x + b.x, a.y + b.y);
        sEO[sl*804 + 396 + k*33 + y1] = make_float2(a.x - b.x, a.y - b.y);
    }
    __syncthreads();

    {
        int ky = tid / 12, kz = tid % 12;
        int p = ky & 1;
        const float2* tw = stY + ky*33;
        const float2* dat0 = sEO + p*396 + kz*33;
        const float2* dat1 = sEO + 804 + p*396 + kz*33;
        u64 acc0 = 0ull, acc1 = 0ull;
#pragma unroll 4
        for (int y1 = 0; y1 < 32; y1++) {
            float2 w = tw[y1];
            u64 cp = pk2(w.x, w.x), sp = pk2(w.y, w.y);
            float2 v0 = dat0[y1];
            fma2(acc0, cp, pk2(v0.x, v0.y));
            fma2(acc0, sp, pk2(v0.y, -v0.x));
            float2 v1 = dat1[y1];
            fma2(acc1, cp, pk2(v1.x, v1.y));
            fma2(acc1, sp, pk2(v1.y, -v1.x));
        }
        int bb = slab0 >> 10, cc = (slab0 >> 6) & 15, xx0 = slab0 & 63;
        float2 r0 = unpk2(acc0), r1 = unpk2(acc1);
        float4* dst = (float4*)(g_Bm + ((size_t)(bb*24 + ky)*12 + kz)*1024 + cc*64 + xx0);
        *dst = make_float4(r0.x, r0.y, r1.x, r1.y);
    }
}

// ---------------- kBC: X-DFT (radix-2) + spectral 16x16 mix + inverse X-DFT, fused  [R12 verbatim] ----------------
__global__ void __launch_bounds__(512) kBC() {
    __shared__ float2 sIn[16*65*2];
    __shared__ float2 sAcc[24*16*2];
    __shared__ float2 sMix[24*16*2];
    __shared__ float2 stX[792];
    int blk = blockIdx.x;
    int b = blk / 144, r = blk % 144;
    int ky = r / 6, q = r % 6;
    int k0 = q * 2;
    int tid = threadIdx.x;

    const float4* src = (const float4*)(g_Bm + ((size_t)(b*24 + ky)*12 + k0)*1024);
    for (int i = tid; i < 1024; i += 512) {
        int kzi = i >> 9, j = i & 511;
        float4 v = src[kzi*512 + j];
        int c = j >> 5, x2 = (j & 31)*2;
        int base = (c*65 + x2)*2 + kzi;
        sIn[base]     = make_float2(v.x, v.y);
        sIn[base + 2] = make_float2(v.z, v.w);
    }
    for (int i = tid; i < 792; i += 512) stX[i] = g_twXY[i];
    __syncthreads();

    float4* sIn4 = (float4*)sIn;
    {
        int c = tid >> 5, x1 = tid & 31;
        float4 a = sIn4[c*65 + x1], bb4 = sIn4[c*65 + x1 + 32];
        sIn4[c*65 + x1]      = make_float4(a.x + bb4.x, a.y + bb4.y, a.z + bb4.z, a.w + bb4.w);
        sIn4[c*65 + x1 + 32] = make_float4(a.x - bb4.x, a.y - bb4.y, a.z - bb4.z, a.w - bb4.w);
    }
    __syncthreads();

    if (tid < 384) {
        int kx = tid >> 4, c = tid & 15;
        const float4* rowp = sIn4 + c*65 + (kx & 1)*32;
        const float2* tw = &stX[kx*33];
        u64 acc0 = 0ull, acc1 = 0ull;
#pragma unroll 4
        for (int x1 = 0; x1 < 32; x1++) {
            float4 v = rowp[x1];
            float2 w = tw[x1];
            u64 cp = pk2(w.x, w.x), sp = pk2(w.y, w.y);
            fma2(acc0, cp, pk2(v.x, v.y));  fma2(acc0, sp, pk2(v.y, -v.x));
            fma2(acc1, cp, pk2(v.z, v.w));  fma2(acc1, sp, pk2(v.w, -v.z));
        }
        float2 a0 = unpk2(acc0), a1 = unpk2(acc1);
        ((float4*)sAcc)[kx*16 + c] = make_float4(a0.x, a0.y, a1.x, a1.y);
    }
    __syncthreads();
    if (tid < 384) {
        int kx = tid >> 4, o = tid & 15;
        float2 dv[2];
#pragma unroll
        for (int kzi = 0; kzi < 2; kzi++) {
            const float2* Wp = g_W + ((size_t)((kx*24 + ky)*12 + k0 + kzi)) * 256;
            float2 acc = make_float2(0.f, 0.f);
#pragma unroll
            for (int i = 0; i < 16; i++) {
                float2 av = sAcc[(kx*16 + i)*2 + kzi];
                float2 w  = Wp[i*16 + o];
                acc.x += av.x*w.x - av.y*w.y;
                acc.y += av.x*w.y + av.y*w.x;
            }
            dv[kzi] = acc;
        }
        ((float4*)sMix)[kx*16 + o] = make_float4(dv[0].x, dv[0].y, dv[1].x, dv[1].y);
    }
    __syncthreads();

    {
        int o = tid >> 5, x1 = tid & 31;
        const u64* stX64 = (const u64*)stX;
        u64 Se[2], So[2];
        Se[0] = Se[1] = So[0] = So[1] = 0ull;
#pragma unroll 4
        for (int kx = 0; kx < 24; kx++) {
            u64 t1 = stX64[kx*33 + x1];
            float2 f = unpk2(t1);
            u64 t2 = pk2(-f.y, f.x);
            u64* tgt = (kx & 1) ? So : Se;
            const float2* dm = sMix + (kx*16 + o)*2;
#pragma unroll
            for (int kzi = 0; kzi < 2; kzi++) {
                float2 d = dm[kzi];
                fma2(tgt[kzi], t1, pk2(d.x, d.x));
                fma2(tgt[kzi], t2, pk2(d.y, d.y));
            }
        }
        float2 se0 = unpk2(Se[0]), so0 = unpk2(So[0]);
        float2 se1 = unpk2(Se[1]), so1 = unpk2(So[1]);
        float4* base = (float4*)(g_Bf + (size_t)((b*16 + o)*24 + ky)*768);
        base[(x1*12 + k0) >> 1]        = make_float4(se0.x + so0.x, se0.y + so0.y,
                                                    se1.x + so1.x, se1.y + so1.y);
        base[((x1 + 32)*12 + k0) >> 1] = make_float4(se0.x - so0.x, se0.y - so0.y,
                                                    se1.x - so1.x, se1.y - so1.y);
    }
}

// ---------------- kD3: fused inv-Y + inv-T + ReLU + 16x16 mix + bias ----------------
// block = (b, xx, y-quarter); grid 2048; 256 threads; 5 blocks/SM target (51-reg cap);
// phase-1 reads g_Bf directly (L1/L2-hot, no sE staging); 24 KB static smem; 2 chunks of 4 y1.
__global__ void __launch_bounds__(256, 5) kD3(const float* __restrict__ lo_w,
                                              const float* __restrict__ lo_b,
                                              float* __restrict__ out) {
    __shared__ u64 sF[1536];            // [(c*8 + line)*12 + k], 16 lines per chunk
    __shared__ u64 sT1[792];            // (c,s) inv twiddles, pad 33
    __shared__ u64 sTi[384];            // inv-T (A,B), [k*32+lane]
    __shared__ u64 sWq[256];
    __shared__ float sB[16];

    int tid = threadIdx.x;
    int blk = blockIdx.x;
    int yq = blk & 3;
    int bx = blk >> 2;                  // b*64 + xx
    int b = bx >> 6, xx = bx & 63;

    for (int i = tid; i < 792; i += 256) sT1[i] = ((const u64*)g_twXY)[i];
    for (int i = tid; i < 384; i += 256) sTi[i] = g_twTi2[i];
    { float w = lo_w[tid]; sWq[tid] = pk2(w, w); }
    if (tid < 16) sB[tid] = lo_b[tid];
    __syncthreads();

    int c  = tid >> 4;                  // phase-1 channel
    int l  = (tid >> 2) & 3;            // phase-1 y1 local (4 per chunk)
    int q  = tid & 3;                   // phase-1 kz triple
    int k0 = q * 3;
    int w    = tid >> 5;                // phase-2 warp = line (0..7)
    int lane = tid & 31;

    const u64* Ebase = (const u64*)g_Bf + ((size_t)(b*16 + c)*24*64 + xx)*12 + k0;

    for (int ch = 0; ch < 2; ch++) {
        // ---- phase 1: inverse Y (parity, deferred rotation); data from gmem (L1-hot) ----
        {
            int y1 = yq*8 + ch*4 + l;
            u64 SeA[3], SeB[3], SoA[3], SoB[3];
#pragma unroll
            for (int z = 0; z < 3; z++) { SeA[z]=0ull; SeB[z]=0ull; SoA[z]=0ull; SoB[z]=0ull; }
#pragma unroll 2
            for (int ky = 0; ky < 24; ky++) {
                u64 t1 = sT1[ky*33 + y1];
                const u64* e = Ebase + (size_t)ky*768;
                if (ky & 1) {
#pragma unroll
                    for (int z = 0; z < 3; z++) {
                        float2 d = unpk2(e[z]);
                        fma2(SoA[z], t1, pk2(d.x, d.x));
                        fma2(SoB[z], t1, pk2(d.y, d.y));
                    }
                } else {
#pragma unroll
                    for (int z = 0; z < 3; z++) {
                        float2 d = unpk2(e[z]);
                        fma2(SeA[z], t1, pk2(d.x, d.x));
                        fma2(SeB[z], t1, pk2(d.y, d.y));
                    }
                }
            }
#pragma unroll
            for (int z = 0; z < 3; z++) {
                float2 aE = unpk2(SeA[z]), bE = unpk2(SeB[z]);
                float2 se = make_float2(aE.x - bE.y, aE.y + bE.x);
                float2 aO = unpk2(SoA[z]), bO = unpk2(SoB[z]);
                float2 so = make_float2(aO.x - bO.y, aO.y + bO.x);
                sF[(c*8 + l)*12 + k0 + z]     = pk2(se.x + so.x, se.y + so.y);
                sF[(c*8 + l + 4)*12 + k0 + z] = pk2(se.x - so.x, se.y - so.y);
            }
        }
        __syncthreads();

        // ---- phase 2: inverse T (parity) + ReLU + packed 1x1 mix; warp = line ----
        {
            int y = yq*8 + ch*4 + (w & 3) + ((w >> 2) * 32);
            u64 p[16];
#pragma unroll
            for (int qt = 0; qt < 4; qt++) {
                u64 aE[4], aO[4];
                aE[0]=aE[1]=aE[2]=aE[3]=0ull;
                aO[0]=aO[1]=aO[2]=aO[3]=0ull;
#pragma unroll
                for (int k2 = 0; k2 < 6; k2++) {
                    u64 tvx = sTi[(2*k2)*32 + lane];
                    u64 tvy = sTi[(2*k2 + 1)*32 + lane];
#pragma unroll
                    for (int c4 = 0; c4 < 4; c4++) {
                        ulonglong2 fv = *(const ulonglong2*)(sF + ((qt*4 + c4)*8 + w)*12 + 2*k2);
                        fma2(aE[c4], fv.x, tvx);
                        fma2(aO[c4], fv.y, tvy);
                    }
                }
#pragma unroll
                for (int c4 = 0; c4 < 4; c4++) {
                    float2 e = unpk2(aE[c4]), o = unpk2(aO[c4]);
                    float Ev = e.x + e.y, Ov = o.x + o.y;
                    p[qt*4 + c4] = pk2(fmaxf(Ev + Ov, 0.f), fmaxf(Ev - Ov, 0.f));
                }
            }
#pragma unroll
            for (int o = 0; o < 16; o++) {
                u64 accA = pk2(sB[o], sB[o]);
                u64 accB = 0ull;
                const u64* wq = sWq + o*16;
#pragma unroll
                for (int c2 = 0; c2 < 4; c2++) {
                    ulonglong2 wv = *(const ulonglong2*)(wq + 2*c2);
                    fma2(accA, wv.x, p[2*c2]);
                    fma2(accA, wv.y, p[2*c2 + 1]);
                }
#pragma unroll
                for (int c2 = 4; c2 < 8; c2++) {
                    ulonglong2 wv = *(const ulonglong2*)(wq + 2*c2);
                    fma2(accB, wv.x, p[2*c2]);
                    fma2(accB, wv.y, p[2*c2 + 1]);
                }
                float2 rv = unpk2(add2(accA, accB));
                float* dst = out + (((size_t)(b*16 + o)*64 + xx)*64 + y)*64;
                dst[lane]      = rv.x;
                dst[lane + 32] = rv.y;
            }
        }
        __syncthreads();
    }
}

// ---------------- launch ----------------
extern "C" void kernel_launch(void* const* d_in, const int* in_sizes, int n_in,
                              void* d_out, int out_size) {
    const float* x    = (const float*)d_in[0];
    const float* w1   = (const float*)d_in[1];
    const float* w2   = (const float*)d_in[2];
    const float* w3   = (const float*)d_in[3];
    const float* w4   = (const float*)d_in[4];
    const float* lo_w = (const float*)d_in[5];
    const float* lo_b = (const float*)d_in[6];
    float* out = (float*)d_out;

    cudaFuncSetAttribute(kA2, cudaFuncAttributeMaxDynamicSharedMemorySize, KA2_SMEM);

    k_initrepack<<<577, 256>>>(w1, w2, w3, w4);
    kA2<<<4096, 288, KA2_SMEM>>>(x);                 // T 64->12 + Y 64->24 fused
    kBC<<<1152, 512>>>();                            // X 64->24 + channel mix + X 24->64 fused
    kD3<<<2048, 256>>>(lo_w, lo_b, out);             // Y 24->64 + T 12->64 + relu + 1x1 (5 blk/SM)
}

// round 15
// speedup vs baseline: 1.4249x; 1.4249x over previous
#include <cuda_runtime.h>
#include <math.h>

#define N3INV (1.0f/262144.0f)
typedef unsigned long long u64;

// ---------------- scratch (static device memory; no allocations) ----------------
__device__ float2 g_Bm[8*24*12*1024];    // 19 MB: fwd Y out, mode-major [((b*24+ky)*12+kz)*1024 + c*64+x]
__device__ float2 g_Bf[8*16*64*24*12];   // 19 MB: inv-X out [(bo*24+ky)*64+x][kz]
__device__ float2 g_W [24*24*12*16*16];  // 14 MB: repacked weights, mode-major
__device__ u64    g_twTpkT[32*12];       // fwd T: (c, -s) packed, TRANSPOSED [t1*12+k] (broadcast use)
__device__ u64    g_twTi2 [12*32];       // inv T: (A, B) packed, [k*32+t]  (per-lane stride-1 use)
__device__ float2 g_twXY [24*33];        // X/Y: (c, s)  [padded stride 33] (fwd + inv shared)

// ---------------- f32x2 packed helpers ----------------
__device__ __forceinline__ u64 pk2(float lo, float hi){
    u64 r; asm("mov.b64 %0, {%1,%2};" : "=l"(r) : "f"(lo), "f"(hi)); return r;
}
__device__ __forceinline__ void fma2(u64& d, u64 a, u64 b){
    asm("fma.rn.f32x2 %0, %1, %2, %0;" : "+l"(d) : "l"(a), "l"(b));
}
__device__ __forceinline__ float2 unpk2(u64 v){
    float2 f; asm("mov.b64 {%0,%1}, %2;" : "=f"(f.x), "=f"(f.y) : "l"(v)); return f;
}

// ---------------- init + repack: blocks 0-575 repack (one quadrant each), block 576 twiddles ----------------
__global__ void __launch_bounds__(256) k_initrepack(const float* __restrict__ w1, const float* __restrict__ w2,
                                                    const float* __restrict__ w3, const float* __restrict__ w4) {
    int tid = threadIdx.x;
    if (blockIdx.x == 576) {
        for (int idx = tid; idx < 384 + 792; idx += 256) {
            if (idx < 384) {
                int k = idx >> 5, t = idx & 31;
                float s, c;
                sincospif((float)((k * t) & 63) / 32.0f, &s, &c);
                g_twTpkT[t*12 + k] = pk2(c, -s);
                g_twTi2[idx] = (k == 0) ? pk2(N3INV, 0.0f)
                                        : pk2(2.0f*c*N3INV, -2.0f*s*N3INV);
            } else {
                int r = idx - 384;
                int j = r / 33, u = r % 33;
                int uu = (u < 32) ? u : 0;
                int f = (j < 12) ? j : j + 40;   // freqs 0..11, 52..63
                float s, c;
                sincospif((float)((f * uu) & 63) / 32.0f, &s, &c);
                g_twXY[r] = make_float2(c, s);
            }
        }
        return;
    }
    int q  = blockIdx.x / 144;
    int rm = blockIdx.x % 144;
    int jx = rm / 12, jy = rm % 12;
    const float* w = (q == 0) ? w1 : (q == 1) ? w2 : (q == 2) ? w3 : w4;
    const float4* src = (const float4*)(w + ((size_t)tid*1728 + (jx*12 + jy)*12)*2);
    float2 r[12];
#pragma unroll
    for (int j = 0; j < 6; j++) {
        float4 v = src[j];
        r[2*j]   = make_float2(v.x, v.y);
        r[2*j+1] = make_float2(v.z, v.w);
    }
    int kxi = jx + ((q & 1) ? 12 : 0);
    int kyi = jy + ((q & 2) ? 12 : 0);
    float2* dst = g_W + ((size_t)(kxi*24 + kyi)*12)*256 + tid;
#pragma unroll
    for (int j = 0; j < 12; j++) dst[j*256] = r[j];
}

// ---------------- kA2: fused T-DFT (radix-2) + Y-DFT (radix-2)  [R12 verbatim] ----------------
#define KA2_SMEM (2*4160*4 + 2*792*8 + 384*8 + 792*8)
__global__ void __launch_bounds__(288, 4) kA2(const float* __restrict__ x) {
    extern __shared__ char smraw[];
    float*  sx  = (float*)smraw;
    float2* sA  = (float2*)(smraw + 2*4160*4);
    u64*    stT = (u64*)(smraw + 2*4160*4 + 2*792*8);          // transposed [t1*12+k]
    float2* stY = (float2*)(smraw + 2*4160*4 + 2*792*8 + 384*8);
    float2* sEO = (float2*)sx;           // reused after T-phase: [sl*804 + p*396 + k*33 + y1]

    int slab0 = blockIdx.x * 2;
    int tid = threadIdx.x;

    const float4* xs = (const float4*)(x + (size_t)slab0 * 4096);
    for (int i = tid; i < 2048; i += 288) {
        float4 v = xs[i];
        int sl = i >> 10, r = i & 1023;
        int yy = r >> 4, t4 = (r & 15) * 4;
        float* row = &sx[sl*4160 + yy*65 + t4];
        row[0] = v.x; row[1] = v.y; row[2] = v.z; row[3] = v.w;
    }
    for (int i = tid; i < 384; i += 288) stT[i] = g_twTpkT[i];
    for (int i = tid; i < 792; i += 288) stY[i] = g_twXY[i];
    __syncthreads();

    if (tid < 256) {
        int sl = tid >> 7, g = (tid >> 6) & 1, yy = tid & 63;
        int kb = g * 6;
        const float* row = &sx[sl*4160 + yy*65];
        u64 acc[6];
#pragma unroll
        for (int j = 0; j < 6; j++) acc[j] = 0ull;
#pragma unroll 4
        for (int t1 = 0; t1 < 32; t1++) {
            float a = row[t1], b = row[t1 + 32];
            float E = a + b, O = a - b;
            u64 pE = pk2(E, E), pO = pk2(O, O);
            const u64* tw = stT + t1*12 + kb;
#pragma unroll
            for (int j2 = 0; j2 < 3; j2++) {
                ulonglong2 tv = *(const ulonglong2*)(tw + 2*j2);
                fma2(acc[2*j2],     tv.x, pE);
                fma2(acc[2*j2 + 1], tv.y, pO);
            }
        }
        float2* dst = sA + sl*792 + yy;
#pragma unroll
        for (int j = 0; j < 6; j++) dst[(kb + j)*66] = unpk2(acc[j]);
    }
    __syncthreads();

    for (int i = tid; i < 768; i += 288) {
        int sl = (i >= 384);
        int r  = i - sl*384;                      // r = k*32 + y1
        int k = r >> 5, y1 = r & 31;
        float2 a = sA[sl*792 + k*66 + y1];
        float2 b = sA[sl*792 + k*66 + 32 + y1];
        sEO[sl*804 + k*33 + y1]       = make_float2(a.x + b.x, a.y + b.y);
        sEO[sl*804 + 396 + k*33 + y1] = make_float2(a.x - b.x, a.y - b.y);
    }
    __syncthreads();

    {
        int ky = tid / 12, kz = tid % 12;
        int p = ky & 1;
        const float2* tw = stY + ky*33;
        const float2* dat0 = sEO + p*396 + kz*33;
        const float2* dat1 = sEO + 804 + p*396 + kz*33;
        u64 acc0 = 0ull, acc1 = 0ull;
#pragma unroll 4
        for (int y1 = 0; y1 < 32; y1++) {
            float2 w = tw[y1];
            u64 cp = pk2(w.x, w.x), sp = pk2(w.y, w.y);
            float2 v0 = dat0[y1];
            fma2(acc0, cp, pk2(v0.x, v0.y));
            fma2(acc0, sp, pk2(v0.y, -v0.x));
            float2 v1 = dat1[y1];
            fma2(acc1, cp, pk2(v1.x, v1.y));
            fma2(acc1, sp, pk2(v1.y, -v1.x));
        }
        int bb = slab0 >> 10, cc = (slab0 >> 6) & 15, xx0 = slab0 & 63;
        float2 r0 = unpk2(acc0), r1 = unpk2(acc1);
        float4* dst = (float4*)(g_Bm + ((size_t)(bb*24 + ky)*12 + kz)*1024 + cc*64 + xx0);
        *dst = make_float4(r0.x, r0.y, r1.x, r1.y);
    }
}

// ---------------- kBC: X-DFT (radix-2) + spectral 16x16 mix + inverse X-DFT, fused  [R12 verbatim] ----------------
__global__ void __launch_bounds__(512) kBC() {
    __shared__ float2 sIn[16*65*2];
    __shared__ float2 sAcc[24*16*2];
    __shared__ float2 sMix[24*16*2];
    __shared__ float2 stX[792];
    int blk = blockIdx.x;
    int b = blk / 144, r = blk % 144;
    int ky = r / 6, q = r % 6;
    int k0 = q * 2;
    int tid = threadIdx.x;

    const float4* src = (const float4*)(g_Bm + ((size_t)(b*24 + ky)*12 + k0)*1024);
    for (int i = tid; i < 1024; i += 512) {
        int kzi = i >> 9, j = i & 511;
        float4 v = src[kzi*512 + j];
        int c = j >> 5, x2 = (j & 31)*2;
        int base = (c*65 + x2)*2 + kzi;
        sIn[base]     = make_float2(v.x, v.y);
        sIn[base + 2] = make_float2(v.z, v.w);
    }
    for (int i = tid; i < 792; i += 512) stX[i] = g_twXY[i];
    __syncthreads();

    float4* sIn4 = (float4*)sIn;
    {
        int c = tid >> 5, x1 = tid & 31;
        float4 a = sIn4[c*65 + x1], bb4 = sIn4[c*65 + x1 + 32];
        sIn4[c*65 + x1]      = make_float4(a.x + bb4.x, a.y + bb4.y, a.z + bb4.z, a.w + bb4.w);
        sIn4[c*65 + x1 + 32] = make_float4(a.x - bb4.x, a.y - bb4.y, a.z - bb4.z, a.w - bb4.w);
    }
    __syncthreads();

    if (tid < 384) {
        int kx = tid >> 4, c = tid & 15;
        const float4* rowp = sIn4 + c*65 + (kx & 1)*32;
        const float2* tw = &stX[kx*33];
        u64 acc0 = 0ull, acc1 = 0ull;
#pragma unroll 4
        for (int x1 = 0; x1 < 32; x1++) {
            float4 v = rowp[x1];
            float2 w = tw[x1];
            u64 cp = pk2(w.x, w.x), sp = pk2(w.y, w.y);
            fma2(acc0, cp, pk2(v.x, v.y));  fma2(acc0, sp, pk2(v.y, -v.x));
            fma2(acc1, cp, pk2(v.z, v.w));  fma2(acc1, sp, pk2(v.w, -v.z));
        }
        float2 a0 = unpk2(acc0), a1 = unpk2(acc1);
        ((float4*)sAcc)[kx*16 + c] = make_float4(a0.x, a0.y, a1.x, a1.y);
    }
    __syncthreads();
    if (tid < 384) {
        int kx = tid >> 4, o = tid & 15;
        float2 dv[2];
#pragma unroll
        for (int kzi = 0; kzi < 2; kzi++) {
            const float2* Wp = g_W + ((size_t)((kx*24 + ky)*12 + k0 + kzi)) * 256;
            float2 acc = make_float2(0.f, 0.f);
#pragma unroll
            for (int i = 0; i < 16; i++) {
                float2 av = sAcc[(kx*16 + i)*2 + kzi];
                float2 w  = Wp[i*16 + o];
                acc.x += av.x*w.x - av.y*w.y;
                acc.y += av.x*w.y + av.y*w.x;
            }
            dv[kzi] = acc;
        }
        ((float4*)sMix)[kx*16 + o] = make_float4(dv[0].x, dv[0].y, dv[1].x, dv[1].y);
    }
    __syncthreads();

    {
        int o = tid >> 5, x1 = tid & 31;
        const u64* stX64 = (const u64*)stX;
        u64 Se[2], So[2];
        Se[0] = Se[1] = So[0] = So[1] = 0ull;
#pragma unroll 4
        for (int kx = 0; kx < 24; kx++) {
            u64 t1 = stX64[kx*33 + x1];
            float2 f = unpk2(t1);
            u64 t2 = pk2(-f.y, f.x);
            u64* tgt = (kx & 1) ? So : Se;
            const float2* dm = sMix + (kx*16 + o)*2;
#pragma unroll
            for (int kzi = 0; kzi < 2; kzi++) {
                float2 d = dm[kzi];
                fma2(tgt[kzi], t1, pk2(d.x, d.x));
                fma2(tgt[kzi], t2, pk2(d.y, d.y));
            }
        }
        float2 se0 = unpk2(Se[0]), so0 = unpk2(So[0]);
        float2 se1 = unpk2(Se[1]), so1 = unpk2(So[1]);
        float4* base = (float4*)(g_Bf + (size_t)((b*16 + o)*24 + ky)*768);
        base[(x1*12 + k0) >> 1]        = make_float4(se0.x + so0.x, se0.y + so0.y,
                                                    se1.x + so1.x, se1.y + so1.y);
        base[((x1 + 32)*12 + k0) >> 1] = make_float4(se0.x - so0.x, se0.y - so0.y,
                                                    se1.x - so1.x, se1.y - so1.y);
    }
}

// ---------------- kD2: fused inv-Y + inv-T + ReLU + 16x16 mix + bias ----------------
// R12 code with y-range split in half: block = (b, xx, y-half); grid 1024; 2 chunks/block.
// Same smem layout/size (2 blocks/SM); sE gmem load duplicated 2x (cheap, DRAM has headroom).
#define KD2_SMEM ((4608 + 6144 + 792 + 384 + 256 + 8)*8)
__global__ void __launch_bounds__(512, 2) kD2(const float* __restrict__ lo_w,
                                              const float* __restrict__ lo_b,
                                              float* __restrict__ out) {
    extern __shared__ u64 sm[];
    u64* sE   = sm;                 // [c*288 + ky*12 + kz] packed (re,im)
    u64* sF   = sE + 4608;          // 2 x 3072: [(buf)*3072 + (c*16 + line)*12 + k]
    u64* sT1  = sF + 6144;          // (c,s) inv twiddles, pad 33
    u64* sTi  = sT1 + 792;          // inv-T (A,B), [k*32+lane]  (conflict-free stride-1)
    u64* sWq  = sTi + 384;          // lo_w dup-packed
    float* sB = (float*)(sWq + 256);

    int tid = threadIdx.x;
    int blk = blockIdx.x;
    int yh  = blk & 1;              // y-half: y1 in [yh*16, yh*16+16)
    int bx  = blk >> 1;             // b*64 + xx
    int b = bx >> 6, xx = bx & 63;

    for (int i = tid; i < 4608; i += 512) {
        int c = i / 288, r = i % 288;              // r = ky*12 + kz
        int ky = r / 12, kz = r % 12;
        sE[i] = ((const u64*)g_Bf)[((size_t)((b*16 + c)*24 + ky)*64 + xx)*12 + kz];
    }
    for (int i = tid; i < 792; i += 512) sT1[i] = ((const u64*)g_twXY)[i];
    for (int i = tid; i < 384; i += 512) sTi[i] = g_twTi2[i];
    if (tid < 256) { float w = lo_w[tid]; sWq[tid] = pk2(w, w); }
    if (tid < 16)  sB[tid] = lo_b[tid];
    __syncthreads();

    int c  = tid >> 5;                 // phase-1 channel (warp-uniform)
    int l  = (tid >> 2) & 7;           // phase-1 y1 local
    int q  = tid & 3;                  // phase-1 kz triple
    int k0 = q * 3;
    int w    = tid >> 5;               // phase-2 warp = line
    int lane = tid & 31;

    for (int a = 0; a < 2; a++) {
        int buf = (a & 1) * 3072;
        // ---- phase 1: inverse Y (parity, deferred rotation), 16 lines into sF[buf] ----
        {
            int y1 = yh*16 + 8*a + l;
            const u64* E = sE + c*288 + k0;
            u64 SeA[3], SeB[3], SoA[3], SoB[3];
#pragma unroll
            for (int z = 0; z < 3; z++) { SeA[z]=0ull; SeB[z]=0ull; SoA[z]=0ull; SoB[z]=0ull; }
#pragma unroll 4
            for (int ky = 0; ky < 24; ky++) {
                u64 t1 = sT1[ky*33 + y1];
                const u64* e = E + ky*12;
                if (ky & 1) {
#pragma unroll
                    for (int z = 0; z < 3; z++) {
                        float2 d = unpk2(e[z]);
                        fma2(SoA[z], t1, pk2(d.x, d.x));
                        fma2(SoB[z], t1, pk2(d.y, d.y));
                    }
                } else {
#pragma unroll
                    for (int z = 0; z < 3; z++) {
                        float2 d = unpk2(e[z]);
                        fma2(SeA[z], t1, pk2(d.x, d.x));
                        fma2(SeB[z], t1, pk2(d.y, d.y));
                    }
                }
            }
#pragma unroll
            for (int z = 0; z < 3; z++) {
                // Σ d*(c,s)-pair -> apply rotation to B once: out = A + (-B.y, B.x)
                float2 aE = unpk2(SeA[z]), bE = unpk2(SeB[z]);
                float2 se = make_float2(aE.x - bE.y, aE.y + bE.x);
                float2 aO = unpk2(SoA[z]), bO = unpk2(SoB[z]);
                float2 so = make_float2(aO.x - bO.y, aO.y + bO.x);
                sF[buf + (c*16 + l)*12 + k0 + z]     = pk2(se.x + so.x, se.y + so.y);
                sF[buf + (c*16 + l + 8)*12 + k0 + z] = pk2(se.x - so.x, se.y - so.y);
            }
        }
        __syncthreads();

        // ---- phase 2: inverse T (parity) + ReLU + packed 1x1 mix; warp = line ----
        // (no trailing barrier: next chunk's phase-1 writes the OTHER sF buffer)
        {
            int y = yh*16 + 8*a + (w & 7) + ((w & 8) ? 32 : 0);
            u64 p[16];
#pragma unroll
            for (int qt = 0; qt < 4; qt++) {
                u64 aE[4], aO[4];
                aE[0]=aE[1]=aE[2]=aE[3]=0ull;
                aO[0]=aO[1]=aO[2]=aO[3]=0ull;
#pragma unroll
                for (int k2 = 0; k2 < 6; k2++) {
                    u64 tvx = sTi[(2*k2)*32 + lane];       // conflict-free stride-1
                    u64 tvy = sTi[(2*k2 + 1)*32 + lane];
#pragma unroll
                    for (int c4 = 0; c4 < 4; c4++) {
                        ulonglong2 fv = *(const ulonglong2*)(sF + buf + ((qt*4 + c4)*16 + w)*12 + 2*k2);
                        fma2(aE[c4], fv.x, tvx);    // k even
                        fma2(aO[c4], fv.y, tvy);    // k odd
                    }
                }
#pragma unroll
                for (int c4 = 0; c4 < 4; c4++) {
                    float2 e = unpk2(aE[c4]), o = unpk2(aO[c4]);
                    float Ev = e.x + e.y, Ov = o.x + o.y;
                    p[qt*4 + c4] = pk2(fmaxf(Ev + Ov, 0.f), fmaxf(Ev - Ov, 0.f));
                }
            }
#pragma unroll
            for (int o = 0; o < 16; o++) {
                u64 acc = pk2(sB[o], sB[o]);
                const u64* wq = sWq + o*16;
#pragma unroll
                for (int c2 = 0; c2 < 8; c2++) {
                    ulonglong2 wv = *(const ulonglong2*)(wq + 2*c2);
                    fma2(acc, wv.x, p[2*c2]);
                    fma2(acc, wv.y, p[2*c2 + 1]);
                }
                float2 rv = unpk2(acc);
                float* dst = out + (((size_t)(b*16 + o)*64 + xx)*64 + y)*64;
                dst[lane]      = rv.x;
                dst[lane + 32] = rv.y;
            }
        }
    }
}

// ---------------- launch ----------------
extern "C" void kernel_launch(void* const* d_in, const int* in_sizes, int n_in,
                              void* d_out, int out_size) {
    const float* x    = (const float*)d_in[0];
    const float* w1   = (const float*)d_in[1];
    const float* w2   = (const float*)d_in[2];
    const float* w3   = (const float*)d_in[3];
    const float* w4   = (const float*)d_in[4];
    const float* lo_w = (const float*)d_in[5];
    const float* lo_b = (const float*)d_in[6];
    float* out = (float*)d_out;

    cudaFuncSetAttribute(kA2, cudaFuncAttributeMaxDynamicSharedMemorySize, KA2_SMEM);
    cudaFuncSetAttribute(kD2, cudaFuncAttributeMaxDynamicSharedMemorySize, KD2_SMEM);

    k_initrepack<<<577, 256>>>(w1, w2, w3, w4);
    kA2<<<4096, 288, KA2_SMEM>>>(x);                 // T 64->12 + Y 64->24 fused
    kBC<<<1152, 512>>>();                            // X 64->24 + channel mix + X 24->64 fused
    kD2<<<1024, 512, KD2_SMEM>>>(lo_w, lo_b, out);   // Y 24->64 + T 12->64 + relu + 1x1 (y-half split)
}